// round 13
// baseline (speedup 1.0000x reference)
#include <cuda_runtime.h>
#include <cuda_fp16.h>
#include <cstdint>

typedef uint32_t u32;

// Fixed dims: 65536 rows, Dn=128, L=256, H=8, DH=32. Only graph branch matters
// (reference loop overwrites `out`; graph branch has T=1 -> rank-1 kv).
// Epilogue folded into GEMM: Q extended to K=288 (c hi/lo lanes + 1-lanes),
// weight stream extended with chunk 12 = [U_hi; U_lo; b_out_hi; b_out_lo; 0].
#define NROWS_TOTAL 65536
#define ROWS_PER_BLK 64
#define THREADS 256
#define NBLKS (NROWS_TOTAL / ROWS_PER_BLK)   // 1024
#define NCHUNKS 13

// ---------------- SMEM layout (bytes) --------------------------------------
// f[0..3327] floats (13312B): [0..255] bnq | [256..511] kvec | [2816..3327] c[64][8]
// X @13312 (17408B fp16 [64][136])
// Q @30720 (37888B fp16 [64][296])   (cols 256..287 = epilogue extension)
// WC @68608: 2 x 20480B chunk buffers ([256][40] half, K=32 each)
#define OFF_X    13312
#define OFF_Q    30720
#define OFF_WC   68608
#define WCBUF    20480
#define SMEM_BYTES 109568   // 2 CTAs/SM (219136 <= 227KB)
#define FI_C 2816

#define XSTR 68     // u32 words/row (272 B); 68%32=4  -> LDSM conflict-free
#define QSTR 148    // u32 words/row (592 B); 148%32=20 -> rows hit distinct banks

// ---------------- device globals (precomputed each launch) -----------------
__device__ float  g_p4part[4 * 128 * 256];     // K-split partials of W_node@Wq
__device__ __half g_Wch[NCHUNKS * 256 * 40];   // 13 K=32 chunks: 0-3 Wnq^T, 4-11 Wout^T, 12 epi
__device__ __half g_X16[NROWS_TOTAL * 136];    // X pre-converted fp16, padded rows
__device__ float g_bnq[256], g_kvec[256];
__device__ float g_kraw[256], g_vraw[256];

// ---------------- helpers ---------------------------------------------------
__device__ __forceinline__ void mma16816(float* d, const u32* a, const u32* b) {
    asm volatile(
        "mma.sync.aligned.m16n8k16.row.col.f32.f16.f16.f32 "
        "{%0,%1,%2,%3}, {%4,%5,%6,%7}, {%8,%9}, {%0,%1,%2,%3};"
        : "+f"(d[0]), "+f"(d[1]), "+f"(d[2]), "+f"(d[3])
        : "r"(a[0]), "r"(a[1]), "r"(a[2]), "r"(a[3]), "r"(b[0]), "r"(b[1]));
}
__device__ __forceinline__ void ldsm4(u32* r, u32 addr) {
    asm volatile("ldmatrix.sync.aligned.m8n8.x4.shared.b16 {%0,%1,%2,%3}, [%4];"
        : "=r"(r[0]), "=r"(r[1]), "=r"(r[2]), "=r"(r[3]) : "r"(addr));
}
__device__ __forceinline__ u32 packh2(float x, float y) {
    __half2 h = __floats2half2_rn(x, y);
    return *reinterpret_cast<u32*>(&h);
}
#define CP16(dst, src) \
    asm volatile("cp.async.cg.shared.global [%0], [%1], 16;" :: "r"(dst), "l"(src))
#define CP_COMMIT() asm volatile("cp.async.commit_group;" ::: "memory")
#define CP_WAIT0()  asm volatile("cp.async.wait_group 0;" ::: "memory")

// ---------------- precompute A: p2 + p4 + p5 + pX merged -------------------
// bid 0..95     p2: lifted-graph + three K=256 GEMVs (warp per output)
// bid 96..607   p4: K-split partials of W_node@Wq
// bid 608..863  p5: W_out -> fp16 chunk layout (chunks 4..11)
// bid 864..2911 pX: node_features fp32 -> padded fp16 rows (float4 loads)
__global__ void pA_kernel(const float* __restrict__ energy,
                          const float* __restrict__ W_graph,
                          const float* __restrict__ b_graph,
                          const float* __restrict__ Wk, const float* __restrict__ bk,
                          const float* __restrict__ Wv, const float* __restrict__ bv,
                          const float* __restrict__ Wq, const float* __restrict__ bq,
                          const float* __restrict__ b_node,
                          const float* __restrict__ W_node,
                          const float* __restrict__ W_out,
                          const float* __restrict__ X)
{
    __shared__ float sh[256];
    const int bid = blockIdx.x;
    const int t = threadIdx.x;

    if (bid < 96) {
        const int warp = t >> 5, lane = t & 31;
        const int oid = bid * 8 + warp;
        const int kind = oid >> 8;
        const int j = oid & 255;
        {
            float acc = b_graph[t];
            #pragma unroll
            for (int d = 0; d < 32; d++) acc += energy[d] * W_graph[d * 256 + t];
            sh[t] = acc;
        }
        __syncthreads();
        const float* W; const float* xv; float bias;
        if (kind == 0)      { W = Wk + 2 * 65536; xv = sh;     bias = bk[512 + j]; }
        else if (kind == 1) { W = Wv + 2 * 65536; xv = sh;     bias = bv[512 + j]; }
        else                { W = Wq;             xv = b_node; bias = bq[j]; }
        float s = 0.0f;
        #pragma unroll
        for (int u = 0; u < 8; u++) { int i = lane + 32 * u; s += xv[i] * W[i * 256 + j]; }
        #pragma unroll
        for (int o = 16; o > 0; o >>= 1) s += __shfl_xor_sync(0xffffffffu, s, o);
        if (lane == 0) {
            s += bias;
            if (kind == 0) g_kraw[j] = s;
            else if (kind == 1) g_vraw[j] = s;
            else g_bnq[j] = s;
        }
    } else if (bid < 608) {
        const int idx = bid - 96;
        const int i = idx & 127, kc = idx >> 7;
        if (t < 64) sh[t] = W_node[i * 256 + kc * 64 + t];
        __syncthreads();
        const float* Wqp = Wq + (kc * 64) * 256 + t;
        float a[8];
        #pragma unroll
        for (int q = 0; q < 8; q++) a[q] = 0.0f;
        #pragma unroll
        for (int m = 0; m < 64; m += 8) {
            #pragma unroll
            for (int q = 0; q < 8; q++)
                a[q] = fmaf(sh[m + q], Wqp[(m + q) * 256], a[q]);
        }
        float r = ((a[0] + a[1]) + (a[2] + a[3])) + ((a[4] + a[5]) + (a[6] + a[7]));
        g_p4part[(kc * 128 + i) * 256 + t] = r;
    } else if (bid < 864) {
        // p5: W_out row m -> chunk (4 + m/32), position m%32, n = t
        const int m = bid - 608;
        g_Wch[(4 + (m >> 5)) * 10240 + t * 40 + (m & 31)] =
            __float2half(W_out[m * 256 + t]);
    } else {
        // pX: 32 rows per block -> padded fp16 (float4 loads)
        const int b = bid - 864;                   // 0..2047
        const float4* xs = (const float4*)(X + (size_t)b * 32 * 128);
        u32* xd = (u32*)g_X16 + (size_t)b * 32 * 68;
        #pragma unroll
        for (int i = 0; i < 4; i++) {
            const int idx = i * 256 + t;           // < 1024 (32 f4 per row)
            const int r = idx >> 5, cp = idx & 31;
            float4 v = xs[idx];
            xd[r * 68 + cp * 2]     = packh2(v.x, v.y);
            xd[r * 68 + cp * 2 + 1] = packh2(v.z, v.w);
        }
    }
}

// ---------------- precompute B: p3 + p6 + epi-chunk merged -----------------
// bid 0      : softmax(kraw) per head
// bid 1..8   : U[h] = v_h @ W_out_h -> chunk 12 rows h (hi) and 8+h (lo)
// bid 9..136 : reduce p4 partials -> Wnq chunks 0..3
// bid 137    : chunk 12 rows 16/17 = b_out hi/lo, rows 18..39 = 0
__global__ void pB_kernel(const float* __restrict__ W_out,
                          const float* __restrict__ b_out)
{
    const int bid = blockIdx.x;
    const int t = threadIdx.x;
    __half* epi = g_Wch + 12 * 10240;
    if (bid == 0) {
        const int w = t >> 5, lane = t & 31;
        float x = g_kraw[w * 32 + lane];
        float m = x;
        #pragma unroll
        for (int o = 16; o > 0; o >>= 1) m = fmaxf(m, __shfl_xor_sync(0xffffffffu, m, o));
        const float e = __expf(x - m);
        float s = e;
        #pragma unroll
        for (int o = 16; o > 0; o >>= 1) s += __shfl_xor_sync(0xffffffffu, s, o);
        g_kvec[w * 32 + lane] = e / s;
    } else if (bid < 9) {
        const int h = bid - 1;
        __shared__ float sv[32];
        if (t < 32) sv[t] = g_vraw[h * 32 + t];
        __syncthreads();
        float u = 0.0f;
        #pragma unroll
        for (int e2 = 0; e2 < 32; e2++) u += sv[e2] * W_out[(h * 32 + e2) * 256 + t];
        __half hi = __float2half(u);
        __half lo = __float2half(u - __half2float(hi));
        epi[t * 40 + h]     = hi;
        epi[t * 40 + 8 + h] = lo;
    } else if (bid < 137) {
        const int j = (bid - 9) * 2 + (t >> 7);
        const int i = t & 127;
        float s = g_p4part[i * 256 + j] + g_p4part[(128 + i) * 256 + j]
                + g_p4part[(256 + i) * 256 + j] + g_p4part[(384 + i) * 256 + j];
        g_Wch[(i >> 5) * 10240 + j * 40 + (i & 31)] = __float2half(s);
    } else {
        float b = b_out[t];
        __half hi = __float2half(b);
        __half lo = __float2half(b - __half2float(hi));
        epi[t * 40 + 16] = hi;
        epi[t * 40 + 17] = lo;
        #pragma unroll
        for (int kl = 18; kl < 40; kl++) epi[t * 40 + kl] = __half(0.0f);
    }
}

// ---------------- main HMMA kernel (256 thr, 64 rows, 2 CTA/SM) ------------
extern __shared__ char s_raw[];

__device__ __forceinline__ void prefetch_chunk(u32 sb, int ck, int tid) {
    const u32 dst = sb + OFF_WC + (u32)(ck & 1) * WCBUF;
    const char* src = (const char*)g_Wch + (size_t)ck * 20480;
    #pragma unroll
    for (int i = 0; i < 5; i++) {
        const int idx = tid + i * 256;            // < 1280
        CP16(dst + (u32)(idx * 16), src + idx * 16);
    }
    CP_COMMIT();
}

__global__ __launch_bounds__(THREADS, 2)
void ghca_main_kernel(float* __restrict__ out)
{
    float* f = (float*)s_raw;
    const u32 sb = (u32)__cvta_generic_to_shared(s_raw);
    const int tid = threadIdx.x;
    const int wid = tid >> 5, lane = tid & 31;
    const int g = lane >> 2, tig = lane & 3;
    const int wr = wid & 1, wc = wid >> 1;     // warp: rows wr*32.., cols wc*64..
    const int row0 = blockIdx.x * ROWS_PER_BLK;

    const int tile = lane >> 3, tr8 = lane & 7;
    const u32 aXbase = sb + OFF_X +
        (u32)((wr * 32 + ((tile & 1) << 3) + tr8) * 272 + ((tile >> 1) << 4));
    const u32 aQbase = sb + OFF_Q +
        (u32)((wr * 32 + ((tile & 1) << 3) + tr8) * 592 + ((tile >> 1) << 4));
    const u32 bWrel =
        (u32)((wc * 64 + ((tile >> 1) << 3) + tr8) * 80 + ((tile & 1) << 4));

    // ---- issue X tile copy (flat, pre-converted): 64 rows = 1088 x 16B ----
    {
        const char* src = (const char*)g_X16 + (size_t)row0 * 272;
        const u32 dst = sb + OFF_X;
        #pragma unroll
        for (int i = 0; i < 4; i++) {
            const int idx = tid + i * 256;
            CP16(dst + (u32)(idx * 16), src + idx * 16);
        }
        if (tid < 64) {
            const int idx = 1024 + tid;
            CP16(dst + (u32)(idx * 16), src + idx * 16);
        }
        CP_COMMIT();
    }
    // ---- chunk 0 ----
    prefetch_chunk(sb, 0, tid);

    // ---- stage small arrays (plain loads; covered by first barrier) ----
    f[tid]       = g_bnq[tid];
    f[256 + tid] = g_kvec[tid];

    float d[2][8][4];
    #pragma unroll
    for (int mt = 0; mt < 2; mt++)
        #pragma unroll
        for (int nt = 0; nt < 8; nt++)
            #pragma unroll
            for (int c = 0; c < 4; c++) d[mt][nt][c] = 0.0f;

    // ---- unified stream: 13 K=32 chunks (0-3: Y=X@Wnq, 4-12: Z=Q'@W') ----
    #pragma unroll 1
    for (int ck = 0; ck < NCHUNKS; ck++) {
        CP_WAIT0();        // chunk ck (and, at ck=0, X) resident
        __syncthreads();
        if (ck < NCHUNKS - 1) prefetch_chunk(sb, ck + 1, tid);

        if (ck == 4) {
            // cooperative write of Q extension cols 256..287 from fc (visible
            // after this iteration's barrier); read only at ck=12.
            u32* Qh = (u32*)(s_raw + OFF_Q);
            const float* fc = f + FI_C;
            #pragma unroll
            for (int i = 0; i < 4; i++) {
                const int idx = tid + i * 256;     // < 1024 = 64 rows x 16 words
                const int r = idx >> 4, w = idx & 15;
                u32 val;
                if (w < 8) {
                    const int h2 = (w & 3) * 2;
                    val = packh2(fc[r * 8 + h2], fc[r * 8 + h2 + 1]);
                } else if (w == 8) {
                    val = packh2(1.0f, 1.0f);
                } else {
                    val = 0u;
                }
                Qh[r * QSTR + 128 + w] = val;
            }
        }

        const bool ph1 = (ck < 4);
        const u32 abase = ph1 ? (aXbase + (u32)(ck * 64))
                              : (aQbase + (u32)((ck - 4) * 64));
        const u32 astr = ph1 ? 272u : 592u;
        const u32 bbase = sb + OFF_WC + (u32)(ck & 1) * WCBUF + bWrel;

        #pragma unroll
        for (int ks = 0; ks < 2; ks++) {
            u32 a0[4], a1[4];
            ldsm4(a0, abase + (u32)(ks * 32));
            ldsm4(a1, abase + 16 * astr + (u32)(ks * 32));
            #pragma unroll
            for (int p = 0; p < 4; p++) {
                u32 b[4];
                ldsm4(b, bbase + (u32)(p * 1280) + (u32)(ks * 32));
                mma16816(d[0][2 * p],     a0, b);
                mma16816(d[0][2 * p + 1], a0, b + 2);
                mma16816(d[1][2 * p],     a1, b);
                mma16816(d[1][2 * p + 1], a1, b + 2);
            }
        }

        if (ck == 3) {
            // ---- softmax (inputs unit-scale; no max pass), build c, Q ----
            // prefetch(4) already in flight above -> overlaps this block
            u32* Qh = (u32*)(s_raw + OFF_Q);
            float* fc = f + FI_C;
            #pragma unroll
            for (int mt = 0; mt < 2; mt++) {
                #pragma unroll
                for (int rh = 0; rh < 2; rh++) {
                    const int row = wr * 32 + mt * 16 + rh * 8 + g;
                    #pragma unroll
                    for (int hg = 0; hg < 2; hg++) {
                        const int head = wc * 2 + hg;
                        float y[8];
                        float s = 0.0f;
                        #pragma unroll
                        for (int q = 0; q < 4; q++) {
                            const int col = wc * 64 + (hg * 4 + q) * 8 + tig * 2;
                            y[q * 2]     = __expf(d[mt][hg * 4 + q][rh * 2]     + f[col]);
                            y[q * 2 + 1] = __expf(d[mt][hg * 4 + q][rh * 2 + 1] + f[col + 1]);
                            s += y[q * 2] + y[q * 2 + 1];
                        }
                        s += __shfl_xor_sync(0xffffffffu, s, 1);
                        s += __shfl_xor_sync(0xffffffffu, s, 2);
                        const float inv = 1.0f / s;
                        float pd = 0.0f;
                        #pragma unroll
                        for (int q = 0; q < 4; q++) {
                            const int col = wc * 64 + (hg * 4 + q) * 8 + tig * 2;
                            y[q * 2]     *= inv;
                            y[q * 2 + 1] *= inv;
                            pd += y[q * 2] * f[256 + col] + y[q * 2 + 1] * f[256 + col + 1];
                        }
                        pd += __shfl_xor_sync(0xffffffffu, pd, 1);
                        pd += __shfl_xor_sync(0xffffffffu, pd, 2);
                        if (tig == 0)
                            fc[row * 8 + head] = (pd >= 1e-8f) ? 1.0f : pd * 1e8f;
                        #pragma unroll
                        for (int q = 0; q < 4; q++) {
                            const int wi = row * QSTR + wc * 32 + (hg * 4 + q) * 4 + tig;
                            Qh[wi] = packh2(y[q * 2], y[q * 2 + 1]);
                        }
                    }
                }
            }
            // reset accumulators for phase 2
            #pragma unroll
            for (int mt = 0; mt < 2; mt++)
                #pragma unroll
                for (int nt = 0; nt < 8; nt++)
                    #pragma unroll
                    for (int c = 0; c < 4; c++) d[mt][nt][c] = 0.0f;
            // Q-write visibility handled by the barrier at top of ck=4
        }
    }

    // ---- epilogue: pure stores (bias + correction folded into chunk 12) ----
    #pragma unroll
    for (int mt = 0; mt < 2; mt++) {
        const int r0 = wr * 32 + mt * 16 + g;
        const int r1 = r0 + 8;
        #pragma unroll
        for (int nt = 0; nt < 8; nt++) {
            const int col = wc * 64 + nt * 8 + tig * 2;
            *(float2*)(out + (size_t)(row0 + r0) * 256 + col) =
                make_float2(d[mt][nt][0], d[mt][nt][1]);
            *(float2*)(out + (size_t)(row0 + r1) * 256 + col) =
                make_float2(d[mt][nt][2], d[mt][nt][3]);
        }
    }
}

// ---------------- launch ----------------------------------------------------
extern "C" void kernel_launch(void* const* d_in, const int* in_sizes, int n_in,
                              void* d_out, int out_size)
{
    const float* node    = (const float*)d_in[0];
    const float* energy  = (const float*)d_in[2];
    const float* W_node  = (const float*)d_in[3];
    const float* b_node  = (const float*)d_in[4];
    const float* W_graph = (const float*)d_in[7];
    const float* b_graph = (const float*)d_in[8];
    const float* Wq      = (const float*)d_in[9];
    const float* bq      = (const float*)d_in[10];
    const float* Wk      = (const float*)d_in[11];
    const float* bk      = (const float*)d_in[12];
    const float* Wv      = (const float*)d_in[13];
    const float* bv      = (const float*)d_in[14];
    const float* W_out   = (const float*)d_in[15];
    const float* b_out   = (const float*)d_in[16];
    float* out = (float*)d_out;

    pA_kernel<<<2912, 256>>>(energy, W_graph, b_graph, Wk, bk, Wv, bv,
                             Wq, bq, b_node, W_node, W_out, node);
    pB_kernel<<<138, 256>>>(W_out, b_out);

    cudaFuncSetAttribute(ghca_main_kernel,
                         cudaFuncAttributeMaxDynamicSharedMemorySize, SMEM_BYTES);
    ghca_main_kernel<<<NBLKS, THREADS, SMEM_BYTES>>>(out);
}